// round 5
// baseline (speedup 1.0000x reference)
#include <cuda_runtime.h>
#include <math.h>
#include <stdint.h>

typedef unsigned long long ull;

// ---------------------------------------------------------------- constants
constexpr int BATCH = 64;
constexpr int SEQ   = 512;
constexpr int WIDTH = 256;   // hidden width
constexpr int EMBED = 512;   // 2*WIDTH
constexpr int ROWS  = BATCH * SEQ;   // 32768 GEMM rows

// ---------------------------------------------------------------- scratch
__device__ float g_bufA[BATCH * SEQ * WIDTH];
__device__ float g_bufB[BATCH * SEQ * WIDTH];

// ---------------------------------------------------------------- f32x2 helpers
__device__ __forceinline__ ull pk2(float lo, float hi) {
    ull r; asm("mov.b64 %0,{%1,%2};" : "=l"(r) : "f"(lo), "f"(hi)); return r;
}
__device__ __forceinline__ void up2(ull v, float& lo, float& hi) {
    asm("mov.b64 {%0,%1},%2;" : "=f"(lo), "=f"(hi) : "l"(v));
}
__device__ __forceinline__ ull ffma2(ull a, ull b, ull c) {
    ull d; asm("fma.rn.f32x2 %0,%1,%2,%3;" : "=l"(d) : "l"(a), "l"(b), "l"(c)); return d;
}

// ============================================================================
// GEMM: C[R, 256] = A[R, K] @ Wm[K, 256] + bias   (unchanged, known-good)
// ============================================================================
template<bool GATHER>
__global__ void __launch_bounds__(512, 1)
gemm_kernel(const int* __restrict__ tokens, const float* __restrict__ A,
            const float* __restrict__ Wm, const float* __restrict__ bias,
            float* __restrict__ C, int K)
{
    __shared__ ull   ATu[16][128];
    __shared__ float Bs[16][128];

    const int tid = threadIdx.x;
    const int r0  = blockIdx.x * 128;
    const int n0  = blockIdx.y * 128;

    const int lrow = tid >> 2;
    const int lkq  = (tid & 3) * 4;
    const float* arow;
    if (GATHER) arow = A + (size_t)tokens[r0 + lrow] * (size_t)K;
    else        arow = A + (size_t)(r0 + lrow) * (size_t)K;

    const int bn = (tid & 31) * 4;
    const int bk = tid >> 5;

    const int ty = tid >> 5;
    const int tx = tid & 31;
    const int cm = ty * 8;
    const int cn = tx * 4;

    ull acc[8][2];
    #pragma unroll
    for (int r = 0; r < 8; r++) { acc[r][0] = 0ull; acc[r][1] = 0ull; }

    #pragma unroll 1
    for (int k0 = 0; k0 < K; k0 += 16) {
        float4 a4 = *(const float4*)(arow + k0 + lkq);
        float4 b4 = *(const float4*)(Wm + (size_t)(k0 + bk) * WIDTH + n0 + bn);
        __syncthreads();
        ATu[lkq + 0][lrow] = pk2(a4.x, a4.x);
        ATu[lkq + 1][lrow] = pk2(a4.y, a4.y);
        ATu[lkq + 2][lrow] = pk2(a4.z, a4.z);
        ATu[lkq + 3][lrow] = pk2(a4.w, a4.w);
        *(float4*)&Bs[bk][bn] = b4;
        __syncthreads();

        #pragma unroll
        for (int kk = 0; kk < 16; kk++) {
            ulonglong2 bv = *(const ulonglong2*)&Bs[kk][cn];
            #pragma unroll
            for (int r = 0; r < 8; r++) {
                ull ad = ATu[kk][cm + r];
                acc[r][0] = ffma2(ad, bv.x, acc[r][0]);
                acc[r][1] = ffma2(ad, bv.y, acc[r][1]);
            }
        }
    }

    const float bv0 = bias[n0 + cn + 0];
    const float bv1 = bias[n0 + cn + 1];
    const float bv2 = bias[n0 + cn + 2];
    const float bv3 = bias[n0 + cn + 3];
    #pragma unroll
    for (int r = 0; r < 8; r++) {
        float c0, c1, c2, c3;
        up2(acc[r][0], c0, c1);
        up2(acc[r][1], c2, c3);
        float4 o = make_float4(c0 + bv0, c1 + bv1, c2 + bv2, c3 + bv3);
        *(float4*)&C[(size_t)(r0 + cm + r) * WIDTH + n0 + cn] = o;
    }
}

// ============================================================================
// RNN scan: ONE CTA per batch row, 512 threads (16 warps).
// Thread (tid): column j = tid>>1, k-half = tid&1 (k in [half*128, half*128+128)).
//  - 48 of its 64 U pairs in registers, 16 in smem (ulonglong2-packed, 2 pairs).
//  - h as plain floats in ping-pong smem; pairs read directly as b64.
//  - lane pair (2j, 2j+1) combines partial sums with one shfl.xor(1).
//  - one __syncthreads per step; no clusters, no mbarriers.
// ============================================================================
constexpr int NREG = 48;                 // U pairs in registers per thread
constexpr int MSM2 = (64 - NREG) / 2;    // 8 ulonglong2 (16 pairs) in smem
constexpr int HSTR = 264;                // floats per h buffer (256 + pad, 16B mult)

constexpr size_t RNN_SMEM = (size_t)2 * MSM2 * 256 * 16   // usm2: 64 KB
                          + 2 * HSTR * 4                  // h ping-pong
                          + 2 * WIDTH * 4;                // reduction scratch

template<bool WRITE_SEQ, bool FINAL>
__global__ void __launch_bounds__(512, 1)
rnn_kernel(const float* __restrict__ xw, const float* __restrict__ U,
           float* __restrict__ hs, const float* __restrict__ Wd,
           const float* __restrict__ bd, float* __restrict__ out)
{
    extern __shared__ unsigned char smraw[];
    ulonglong2* usm2 = (ulonglong2*)smraw;                           // [2][MSM2][256]
    float* hbuf = (float*)(smraw + (size_t)2 * MSM2 * 256 * 16);     // [2][HSTR]
    float* red  = hbuf + 2 * HSTR;                                   // [2][WIDTH]

    const int b    = blockIdx.x;
    const int tid  = threadIdx.x;
    const int half = tid & 1;
    const int j    = tid >> 1;          // output column 0..255
    const int kb   = half * 128;        // k-range base

    // ---- load U: 48 pairs into registers
    ull ureg[NREG];
    #pragma unroll
    for (int m = 0; m < NREG; m++)
        ureg[m] = pk2(U[(size_t)(kb + 2 * m) * WIDTH + j],
                      U[(size_t)(kb + 2 * m + 1) * WIDTH + j]);
    // ---- remaining 16 pairs into smem, 2 pairs per ulonglong2
    #pragma unroll
    for (int mm = 0; mm < MSM2; mm++) {
        const int p0 = NREG + 2 * mm;
        ulonglong2 v;
        v.x = pk2(U[(size_t)(kb + 2 * p0 + 0) * WIDTH + j],
                  U[(size_t)(kb + 2 * p0 + 1) * WIDTH + j]);
        v.y = pk2(U[(size_t)(kb + 2 * p0 + 2) * WIDTH + j],
                  U[(size_t)(kb + 2 * p0 + 3) * WIDTH + j]);
        usm2[(half * MSM2 + mm) * 256 + j] = v;
    }

    if (tid < 256) hbuf[tid] = 0.0f;
    __syncthreads();

    const float* xb = xw + (size_t)b * SEQ * WIDTH + j;
    float xt_next = (half == 0) ? xb[0] : 0.0f;   // only half0 needs xt
    int rd = 0;

    const ulonglong2* myusm = usm2 + (half * MSM2) * 256 + j;

    #pragma unroll 1
    for (int t = 0; t < SEQ; t++) {
        const float xt = xt_next;
        if (half == 0 && t + 1 < SEQ) xt_next = xb[(size_t)(t + 1) * WIDTH];

        const ull* hp = (const ull*)(hbuf + rd * HSTR) + half * 64;  // 64 pairs
        ull a0 = 0ull, a1 = 0ull, a2 = 0ull, a3 = 0ull;

        #pragma unroll
        for (int m = 0; m < NREG; m += 4) {
            ulonglong2 h01 = *(const ulonglong2*)(hp + m);
            ulonglong2 h23 = *(const ulonglong2*)(hp + m + 2);
            a0 = ffma2(h01.x, ureg[m + 0], a0);
            a1 = ffma2(h01.y, ureg[m + 1], a1);
            a2 = ffma2(h23.x, ureg[m + 2], a2);
            a3 = ffma2(h23.y, ureg[m + 3], a3);
        }
        #pragma unroll
        for (int mm = 0; mm < MSM2; mm++) {
            ulonglong2 hh = *(const ulonglong2*)(hp + NREG + 2 * mm);
            ulonglong2 uu = myusm[mm * 256];
            a0 = ffma2(hh.x, uu.x, a0);
            a1 = ffma2(hh.y, uu.y, a1);
        }

        float s0, s1, s2, s3, s4, s5, s6, s7;
        up2(a0, s0, s1); up2(a1, s2, s3); up2(a2, s4, s5); up2(a3, s6, s7);
        float s = (((s0 + s1) + (s2 + s3)) + ((s4 + s5) + (s6 + s7)));
        // combine the two k-halves (lanes 2j / 2j+1)
        s += __shfl_xor_sync(0xFFFFFFFFu, s, 1);

        if (half == 0) {
            const float pre = xt + s;
            // fast tanh: 1 - 2/(e^{2x}+1); exact at +/-inf, ~1e-6 abs err
            const float e  = __expf(2.0f * pre);
            const float hn = 1.0f - __fdividef(2.0f, e + 1.0f);
            hbuf[(rd ^ 1) * HSTR + j] = hn;
            if (WRITE_SEQ)
                hs[(size_t)b * SEQ * WIDTH + (size_t)t * WIDTH + j] = hn;
        }
        __syncthreads();
        rd ^= 1;
    }

    if (FINAL) {
        if (tid < 256) {
            const float h = hbuf[rd * HSTR + tid];
            red[tid]         = h * Wd[tid * 2 + 0];
            red[WIDTH + tid] = h * Wd[tid * 2 + 1];
        }
        __syncthreads();
        #pragma unroll
        for (int sft = 128; sft > 0; sft >>= 1) {
            if (tid < sft) {
                red[tid]         += red[tid + sft];
                red[WIDTH + tid] += red[WIDTH + tid + sft];
            }
            __syncthreads();
        }
        if (tid == 0) {
            const float l0 = red[0] + bd[0];
            const float l1 = red[WIDTH] + bd[1];
            const float mx = fmaxf(l0, l1);
            const float e0 = expf(l0 - mx);
            const float e1 = expf(l1 - mx);
            const float inv = 1.0f / (e0 + e1);
            out[b * 2 + 0] = e0 * inv;
            out[b * 2 + 1] = e1 * inv;
        }
    }
}

// ============================================================================
// launcher
// ============================================================================
extern "C" void kernel_launch(void* const* d_in, const int* in_sizes, int n_in,
                              void* d_out, int out_size)
{
    const int*   tokens = (const int*)  d_in[0];
    const float* emb    = (const float*)d_in[1];
    const float* W1     = (const float*)d_in[2];
    const float* U1     = (const float*)d_in[3];
    const float* b1     = (const float*)d_in[4];
    const float* W2     = (const float*)d_in[5];
    const float* U2     = (const float*)d_in[6];
    const float* b2     = (const float*)d_in[7];
    const float* Wd     = (const float*)d_in[8];
    const float* bd     = (const float*)d_in[9];
    float* out = (float*)d_out;

    float* bufA; cudaGetSymbolAddress((void**)&bufA, g_bufA);
    float* bufB; cudaGetSymbolAddress((void**)&bufB, g_bufB);

    cudaFuncSetAttribute(rnn_kernel<true, false>,
                         cudaFuncAttributeMaxDynamicSharedMemorySize, (int)RNN_SMEM);
    cudaFuncSetAttribute(rnn_kernel<false, true>,
                         cudaFuncAttributeMaxDynamicSharedMemorySize, (int)RNN_SMEM);

    dim3 ggrid(ROWS / 128, WIDTH / 128);   // (256, 2)

    // 1) xw1 = emb[tokens] @ W1 + b1  -> bufA
    gemm_kernel<true><<<ggrid, 512>>>(tokens, emb, W1, b1, bufA, EMBED);

    // 2) RNN1 scan -> h1 sequence in bufB
    rnn_kernel<true, false><<<BATCH, 512, RNN_SMEM>>>(bufA, U1, bufB,
                                                      nullptr, nullptr, nullptr);

    // 3) xw2 = h1 @ W2 + b2 -> bufA
    gemm_kernel<false><<<ggrid, 512>>>(nullptr, bufB, W2, b2, bufA, WIDTH);

    // 4) RNN2 scan, fused dense + softmax -> out
    rnn_kernel<false, true><<<BATCH, 512, RNN_SMEM>>>(bufA, U2, nullptr,
                                                      Wd, bd, out);

    (void)in_sizes; (void)n_in; (void)out_size;
}